// round 8
// baseline (speedup 1.0000x reference)
#include <cuda_runtime.h>
#include <stdint.h>

// Output: [B, C, X, Y] fp32
#define BB 4
#define CC 256
#define XX 256
#define YY 256
#define XY (XX * YY)

// Inverse index: dense cell (b,x,y) -> (feature row + 1), 0 = empty. 1 MB.
// Zero-initialized at module load; the LAST sibling gather block of each
// (b,x) row zeroes its slice again at kernel end, so every launch starts
// from all-zero state. d_cnt likewise returns to zero every launch.
__device__ int d_inv[BB * XX * YY];
__device__ int d_cnt[BB * XX];

// ---------------------------------------------------------------------------
// Kernel 1: scatter (row index + 1) into d_inv. Bounds-guarded = mode="drop".
// 4 points per thread; coords staged through smem with fully-coalesced int4
// loads (3 x 256 int4 per block) for ILP and clean global access.
// ---------------------------------------------------------------------------
__global__ void __launch_bounds__(256)
build_inv_kernel(const int* __restrict__ coords, int n) {
    __shared__ int s_c[3072];            // 1024 points * 3 ints = 12 KB

    const int tid = threadIdx.x;
    const int p0  = blockIdx.x << 10;    // first point of this block
    const int i4base = (3 * p0) >> 2;    // int4 offset (3072*blk % 4 == 0)
    const int n4 = (3 * n + 3) >> 2;     // total int4s in coords

    #pragma unroll
    for (int k = 0; k < 3; k++) {
        const int i4 = i4base + (k << 8) + tid;
        int4 v = make_int4(0, 0, 0, 0);
        if (i4 < n4) v = reinterpret_cast<const int4*>(coords)[i4];
        reinterpret_cast<int4*>(s_c)[(k << 8) + tid] = v;
    }
    __syncthreads();

    #pragma unroll
    for (int e = 0; e < 4; e++) {
        const int p = p0 + (tid << 2) + e;
        if (p < n) {
            const int o = ((tid << 2) + e) * 3;
            const int b = s_c[o + 0];
            const int x = s_c[o + 1];
            const int y = s_c[o + 2];
            if ((unsigned)b < BB && (unsigned)x < XX && (unsigned)y < YY) {
                d_inv[(b * XX + x) * YY + y] = p + 1;
            }
        }
    }
}

// ---------------------------------------------------------------------------
// Kernel 2: row-locality gather with fused inv reset.
// One block = ALL 256 y cells of one (b, x) row x ONE 32-channel group cg
// (cg = fastest grid dim -> 8 siblings co-resident: reads of each feats row
// cluster in time; each block writes 1 KB contiguous per channel plane).
//
// Reset fusion: after staging s_inv (+__syncthreads), thread 0 increments
// d_cnt[bx]; the 8th-arriving sibling (all siblings' inv reads complete)
// zeroes the 256-entry slice and the counter at kernel end. Same output
// regardless of arrival order -> deterministic; state restored every launch.
//
// Tile: float4 tile4[256][8] (32 KB); (j = y cell, q = float4 chunk) at
// column q ^ ((j>>2) & 7) -> conflict-free in cp.async fill AND in the
// store-phase scalar transpose reads (bank (w^l7)*4+l3 spans all 32).
// ---------------------------------------------------------------------------
__global__ void __launch_bounds__(256)
gather_kernel(const float* __restrict__ feats, float* __restrict__ out) {
    __shared__ int    s_inv[YY];
    __shared__ int    s_last;
    __shared__ float4 tile4[YY * 8];     // 32 KB

    const int cg = blockIdx.x & 7;       // channel group (32 channels)
    const int bx = blockIdx.x >> 3;      // b*256 + x
    const int b  = bx >> 8;
    const int x  = bx & 255;
    const int L  = bx * YY;              // linear cell base of this (b,x) row

    const int tid = threadIdx.x;

    // Stage this row's inverse indices (shared by the 8 sibling blocks).
    s_inv[tid] = d_inv[L + tid];
    __syncthreads();                     // all inv loads of this block done

    if (tid == 0) {
        s_last = (atomicAdd(&d_cnt[bx], 1) == 7) ? 1 : 0;
    }

    // ---- load phase: 8 independent cp.async per thread ----
    const int q  = tid & 7;              // 16 B chunk within 128 B
    const int jb = tid >> 3;             // 0..31: cell within wave
    const int csrc = cg * 32 + (q << 2); // first channel of this chunk

    #pragma unroll
    for (int wave = 0; wave < 8; wave++) {
        const int j = (wave << 5) + jb;  // y cell 0..255
        const int r = s_inv[j];
        const float* src = r ? feats + (size_t)(r - 1) * CC + csrc
                             : feats;    // valid addr even when size==0
        const int size = r ? 16 : 0;     // 0 -> zero-fill 16 B
        const uint32_t dst = (uint32_t)__cvta_generic_to_shared(
            &tile4[(j << 3) + (q ^ ((j >> 2) & 7))]);
        asm volatile("cp.async.cg.shared.global [%0], [%1], 16, %2;"
                     :: "r"(dst), "l"(src), "r"(size));
    }
    asm volatile("cp.async.commit_group;");
    asm volatile("cp.async.wait_group 0;");
    __syncthreads();                     // tile ready; s_last visible

    // ---- store phase: 1 KB contiguous per channel, STG.128 full lines ----
    const int w  = tid >> 5;             // warp 0..7 -> channels 4w..4w+3
    const int l  = tid & 31;
    const int l7 = l & 7;
    const int l3 = l >> 3;
    const int colf = ((w ^ l7) << 2) + l3;   // float col within 128 B row

    const float* tf = reinterpret_cast<const float*>(tile4);
    float* op = out + ((size_t)b * CC + cg * 32 + (w << 2) + l3) * XY
                    + (size_t)x * YY + (l7 << 2);

    #pragma unroll
    for (int i = 0; i < 8; i++) {
        const int jbase = (i << 5) + (l7 << 2);  // y = 32i + 4*l7
        float4 v;
        v.x = tf[(jbase + 0) * 32 + colf];
        v.y = tf[(jbase + 1) * 32 + colf];
        v.z = tf[(jbase + 2) * 32 + colf];
        v.w = tf[(jbase + 3) * 32 + colf];
        __stcs(reinterpret_cast<float4*>(op + (i << 5)), v);
    }

    // ---- fused reset: last sibling restores inv slice + counter to 0 ----
    if (s_last) {
        d_inv[L + tid] = 0;
        if (tid == 0) d_cnt[bx] = 0;
    }
}

// ---------------------------------------------------------------------------
// Launcher
// ---------------------------------------------------------------------------
extern "C" void kernel_launch(void* const* d_in, const int* in_sizes, int n_in,
                              void* d_out, int out_size) {
    const float* feats  = (const float*)d_in[0];
    const int*   coords = (const int*)d_in[1];
    float*       out    = (float*)d_out;

    const int n = in_sizes[1] / 3;  // number of sparse points

    build_inv_kernel<<<(n + 1023) / 1024, 256>>>(coords, n);
    gather_kernel<<<BB * XX * 8, 256>>>(feats, out);
}